// round 7
// baseline (speedup 1.0000x reference)
#include <cuda_runtime.h>
#include <cstdint>

constexpr int N_IN  = 256;
constexpr int BATCH = 4096;
constexpr int ITER  = 4;
constexpr int TPB   = 256;   // 128 matrices * 2 row-pairs per block
constexpr int HALF  = 128;

// 256 matrices * 16 floats = 16 KB
__device__ __align__(32) float g_WM[N_IN * 16];

struct V8 { uint32_t r[8]; };

__device__ __forceinline__ V8 ldg256_el(const void* p) {
    V8 v;
    asm volatile("ld.global.nc.L2::evict_last.v8.b32 {%0,%1,%2,%3,%4,%5,%6,%7}, [%8];"
                 : "=r"(v.r[0]), "=r"(v.r[1]), "=r"(v.r[2]), "=r"(v.r[3]),
                   "=r"(v.r[4]), "=r"(v.r[5]), "=r"(v.r[6]), "=r"(v.r[7])
                 : "l"(p));
    return v;
}
__device__ __forceinline__ V8 ldg256(const void* p) {
    V8 v;
    asm volatile("ld.global.nc.v8.b32 {%0,%1,%2,%3,%4,%5,%6,%7}, [%8];"
                 : "=r"(v.r[0]), "=r"(v.r[1]), "=r"(v.r[2]), "=r"(v.r[3]),
                   "=r"(v.r[4]), "=r"(v.r[5]), "=r"(v.r[6]), "=r"(v.r[7])
                 : "l"(p));
    return v;
}
__device__ __forceinline__ void stg256_ef(void* p, const V8& v) {
    asm volatile("st.global.L2::evict_first.v8.b32 [%0], {%1,%2,%3,%4,%5,%6,%7,%8};"
                 :: "l"(p),
                    "r"(v.r[0]), "r"(v.r[1]), "r"(v.r[2]), "r"(v.r[3]),
                    "r"(v.r[4]), "r"(v.r[5]), "r"(v.r[6]), "r"(v.r[7])
                 : "memory");
}

__global__ void build_wm_kernel(const float* __restrict__ aW,
                                const float* __restrict__ uW,
                                const float* __restrict__ tW) {
    int n = threadIdx.x;

    float a  = aW[n];
    float ux = 1.0f / (1.0f + __expf(-uW[n * 3 + 0]));
    float uy = 1.0f / (1.0f + __expf(-uW[n * 3 + 1]));
    float uz = 1.0f / (1.0f + __expf(-uW[n * 3 + 2]));
    float inv = rsqrtf(ux * ux + uy * uy + uz * uz);
    ux *= inv; uy *= inv; uz *= inv;

    float s = __sinf(a);
    float c = __cosf(a);

    float4* W = (float4*)&g_WM[n * 16];
    W[0] = make_float4((1.0f - ux * ux) * c + ux * ux,
                       -uz * s - ux * uy * c + ux * uy,
                        uy * s - ux * uz * c + ux * uz,
                        tW[n * 3 + 0]);
    W[1] = make_float4( uz * s - ux * uy * c + ux * uy,
                       (1.0f - uy * uy) * c + uy * uy,
                       -ux * s - uy * uz * c + uy * uz,
                        tW[n * 3 + 1]);
    W[2] = make_float4(-uy * s - ux * uz * c + ux * uz,
                        ux * s - uy * uz * c + uy * uz,
                       (1.0f - uz * uz) * c + uz * uz,
                        tW[n * 3 + 2]);
    W[3] = make_float4(0.0f, 0.0f, 0.0f, 1.0f);
}

__global__ void __launch_bounds__(TPB) apply_kernel(
    const float* __restrict__ I,
    float* __restrict__ O)
{
    const int tid = threadIdx.x;
    const int h   = blockIdx.x & 1;           // which half of N_IN
    const int g   = blockIdx.x >> 1;          // batch group (0..1023)

    const int n = h * HALF + (tid >> 1);

    // ---- load full WM[n] (64 B) — L1-broadcast-hot, no math ----
    V8 wa = ldg256(&g_WM[n * 16]);      // rows 0,1
    V8 wb = ldg256(&g_WM[n * 16 + 8]);  // rows 2,3
    float4 r0 = make_float4(__uint_as_float(wa.r[0]), __uint_as_float(wa.r[1]),
                            __uint_as_float(wa.r[2]), __uint_as_float(wa.r[3]));
    float4 r1 = make_float4(__uint_as_float(wa.r[4]), __uint_as_float(wa.r[5]),
                            __uint_as_float(wa.r[6]), __uint_as_float(wa.r[7]));
    float4 r2 = make_float4(__uint_as_float(wb.r[0]), __uint_as_float(wb.r[1]),
                            __uint_as_float(wb.r[2]), __uint_as_float(wb.r[3]));
    float4 r3 = make_float4(__uint_as_float(wb.r[4]), __uint_as_float(wb.r[5]),
                            __uint_as_float(wb.r[6]), __uint_as_float(wb.r[7]));

    // ---- stream ITER batches, one 32B load/store per iteration, MLP=4 ----
    constexpr int STRIDE_F = N_IN * 16;        // 4096 floats per batch
    int fidx = g * (ITER * STRIDE_F) + n * 16 + (tid & 1) * 8;

    V8 in[4];
#pragma unroll
    for (int k = 0; k < 4; k++) in[k] = ldg256_el(I + fidx + k * STRIDE_F);

#pragma unroll
    for (int k = 0; k < 4; k++) {
        V8 ov;
#pragma unroll
        for (int half = 0; half < 2; half++) {
            float vx = __uint_as_float(in[k].r[half * 4 + 0]);
            float vy = __uint_as_float(in[k].r[half * 4 + 1]);
            float vz = __uint_as_float(in[k].r[half * 4 + 2]);
            float vw = __uint_as_float(in[k].r[half * 4 + 3]);
            ov.r[half * 4 + 0] = __float_as_uint(fmaf(vx, r0.x, fmaf(vy, r1.x, fmaf(vz, r2.x, vw * r3.x))));
            ov.r[half * 4 + 1] = __float_as_uint(fmaf(vx, r0.y, fmaf(vy, r1.y, fmaf(vz, r2.y, vw * r3.y))));
            ov.r[half * 4 + 2] = __float_as_uint(fmaf(vx, r0.z, fmaf(vy, r1.z, fmaf(vz, r2.z, vw * r3.z))));
            ov.r[half * 4 + 3] = __float_as_uint(fmaf(vx, r0.w, fmaf(vy, r1.w, fmaf(vz, r2.w, vw * r3.w))));
        }
        stg256_ef(O + fidx + k * STRIDE_F, ov);
    }
}

extern "C" void kernel_launch(void* const* d_in, const int* in_sizes, int n_in,
                              void* d_out, int out_size) {
    const float* I  = (const float*)d_in[0];
    const float* aW = (const float*)d_in[1];
    const float* uW = (const float*)d_in[2];
    const float* tW = (const float*)d_in[3];

    build_wm_kernel<<<1, N_IN>>>(aW, uW, tW);

    int blocks = (BATCH / ITER) * 2;   // 2048
    apply_kernel<<<blocks, TPB>>>(I, (float*)d_out);
}

// round 8
// speedup vs baseline: 1.3200x; 1.3200x over previous
#include <cuda_runtime.h>
#include <cstdint>

constexpr int N_IN  = 256;
constexpr int BATCH = 4096;
constexpr int ITER  = 16;
constexpr int TPB   = 256;   // 128 matrices * 2 row-pairs per block
constexpr int HALF  = 128;   // matrices per block

struct V8 { uint32_t r[8]; };

// non-volatile: pure load, let ptxas hoist/batch
__device__ __forceinline__ V8 ldg256_el(const void* p) {
    V8 v;
    asm("ld.global.nc.L2::evict_last.v8.b32 {%0,%1,%2,%3,%4,%5,%6,%7}, [%8];"
        : "=r"(v.r[0]), "=r"(v.r[1]), "=r"(v.r[2]), "=r"(v.r[3]),
          "=r"(v.r[4]), "=r"(v.r[5]), "=r"(v.r[6]), "=r"(v.r[7])
        : "l"(p));
    return v;
}
__device__ __forceinline__ void stg256_ef(void* p, const V8& v) {
    asm volatile("st.global.L2::evict_first.v8.b32 [%0], {%1,%2,%3,%4,%5,%6,%7,%8};"
                 :: "l"(p),
                    "r"(v.r[0]), "r"(v.r[1]), "r"(v.r[2]), "r"(v.r[3]),
                    "r"(v.r[4]), "r"(v.r[5]), "r"(v.r[6]), "r"(v.r[7])
                 : "memory");
}

__global__ void __launch_bounds__(TPB) fused_kernel(
    const float* __restrict__ I,
    const float* __restrict__ aW,
    const float* __restrict__ uW,
    const float* __restrict__ tW,
    float* __restrict__ O)
{
    const int tid = threadIdx.x;
    const int h   = blockIdx.x & 1;           // which half of N_IN
    const int g   = blockIdx.x >> 1;          // batch group (0..255)

    // ---- every thread builds its WM[n] in registers (fast-math MUFU) ----
    const int n = h * HALF + (tid >> 1);

    float a  = aW[n];
    float ex = __expf(-uW[n * 3 + 0]);
    float ey = __expf(-uW[n * 3 + 1]);
    float ez = __expf(-uW[n * 3 + 2]);
    float ux = __frcp_rn(1.0f + ex);
    float uy = __frcp_rn(1.0f + ey);
    float uz = __frcp_rn(1.0f + ez);
    float inv = rsqrtf(fmaf(ux, ux, fmaf(uy, uy, uz * uz)));
    ux *= inv; uy *= inv; uz *= inv;

    float s = __sinf(a);
    float c = __cosf(a);

    float4 r0, r1, r2, r3;
    r0.x = (1.0f - ux * ux) * c + ux * ux;
    r0.y = -uz * s - ux * uy * c + ux * uy;
    r0.z =  uy * s - ux * uz * c + ux * uz;
    r0.w = tW[n * 3 + 0];
    r1.x =  uz * s - ux * uy * c + ux * uy;
    r1.y = (1.0f - uy * uy) * c + uy * uy;
    r1.z = -ux * s - uy * uz * c + uy * uz;
    r1.w = tW[n * 3 + 1];
    r2.x = -uy * s - ux * uz * c + ux * uz;
    r2.y =  ux * s - uy * uz * c + uy * uz;
    r2.z = (1.0f - uz * uz) * c + uz * uz;
    r2.w = tW[n * 3 + 2];
    r3 = make_float4(0.0f, 0.0f, 0.0f, 1.0f);

    // ---- stream ITER batches, one 32B load/store per iteration, MLP=4 ----
    constexpr int STRIDE_F = N_IN * 16;        // 4096 floats per batch
    int fidx = g * (ITER * STRIDE_F) + n * 16 + (tid & 1) * 8;

#pragma unroll
    for (int jj = 0; jj < ITER / 4; jj++) {
        V8 in[4];
#pragma unroll
        for (int k = 0; k < 4; k++) in[k] = ldg256_el(I + fidx + k * STRIDE_F);

#pragma unroll
        for (int k = 0; k < 4; k++) {
            V8 ov;
#pragma unroll
            for (int half = 0; half < 2; half++) {
                float vx = __uint_as_float(in[k].r[half * 4 + 0]);
                float vy = __uint_as_float(in[k].r[half * 4 + 1]);
                float vz = __uint_as_float(in[k].r[half * 4 + 2]);
                float vw = __uint_as_float(in[k].r[half * 4 + 3]);
                ov.r[half * 4 + 0] = __float_as_uint(fmaf(vx, r0.x, fmaf(vy, r1.x, fmaf(vz, r2.x, vw * r3.x))));
                ov.r[half * 4 + 1] = __float_as_uint(fmaf(vx, r0.y, fmaf(vy, r1.y, fmaf(vz, r2.y, vw * r3.y))));
                ov.r[half * 4 + 2] = __float_as_uint(fmaf(vx, r0.z, fmaf(vy, r1.z, fmaf(vz, r2.z, vw * r3.z))));
                ov.r[half * 4 + 3] = __float_as_uint(fmaf(vx, r0.w, fmaf(vy, r1.w, fmaf(vz, r2.w, vw * r3.w))));
            }
            stg256_ef(O + fidx + k * STRIDE_F, ov);
        }
        fidx += 4 * STRIDE_F;
    }
}

extern "C" void kernel_launch(void* const* d_in, const int* in_sizes, int n_in,
                              void* d_out, int out_size) {
    const float* I  = (const float*)d_in[0];
    const float* aW = (const float*)d_in[1];
    const float* uW = (const float*)d_in[2];
    const float* tW = (const float*)d_in[3];

    int blocks = (BATCH / ITER) * 2;   // 512
    fused_kernel<<<blocks, TPB>>>(I, aW, uW, tW, (float*)d_out);
}

// round 9
// speedup vs baseline: 1.3378x; 1.0135x over previous
#include <cuda_runtime.h>
#include <cstdint>

constexpr int N_IN  = 256;
constexpr int BATCH = 4096;
constexpr int ITER  = 16;
constexpr int GRP   = 8;     // batches per load-burst (MLP=8)
constexpr int TPB   = 256;   // 128 matrices * 2 row-pairs per block
constexpr int HALF  = 128;   // matrices per block

struct V8 { uint32_t r[8]; };

__device__ __forceinline__ V8 ldg256_el(const void* p) {
    V8 v;
    asm("ld.global.nc.L2::evict_last.v8.b32 {%0,%1,%2,%3,%4,%5,%6,%7}, [%8];"
        : "=r"(v.r[0]), "=r"(v.r[1]), "=r"(v.r[2]), "=r"(v.r[3]),
          "=r"(v.r[4]), "=r"(v.r[5]), "=r"(v.r[6]), "=r"(v.r[7])
        : "l"(p));
    return v;
}
__device__ __forceinline__ void stg256_ef(void* p, const V8& v) {
    asm volatile("st.global.L2::evict_first.v8.b32 [%0], {%1,%2,%3,%4,%5,%6,%7,%8};"
                 :: "l"(p),
                    "r"(v.r[0]), "r"(v.r[1]), "r"(v.r[2]), "r"(v.r[3]),
                    "r"(v.r[4]), "r"(v.r[5]), "r"(v.r[6]), "r"(v.r[7])
                 : "memory");
}

__global__ void __launch_bounds__(TPB) fused_kernel(
    const float* __restrict__ I,
    const float* __restrict__ aW,
    const float* __restrict__ uW,
    const float* __restrict__ tW,
    float* __restrict__ O)
{
    const int tid = threadIdx.x;
    const int h   = blockIdx.x & 1;           // which half of N_IN
    const int g   = blockIdx.x >> 1;          // batch group (0..255)

    // ---- build WM[n] in registers (MUFU fast path) ----
    const int n = h * HALF + (tid >> 1);

    float a  = aW[n];
    float ex = __expf(-uW[n * 3 + 0]);
    float ey = __expf(-uW[n * 3 + 1]);
    float ez = __expf(-uW[n * 3 + 2]);
    float ux = __frcp_rn(1.0f + ex);
    float uy = __frcp_rn(1.0f + ey);
    float uz = __frcp_rn(1.0f + ez);
    float inv = rsqrtf(fmaf(ux, ux, fmaf(uy, uy, uz * uz)));
    ux *= inv; uy *= inv; uz *= inv;

    float s = __sinf(a);
    float c = __cosf(a);

    float4 r0, r1, r2, r3;
    r0.x = (1.0f - ux * ux) * c + ux * ux;
    r0.y = -uz * s - ux * uy * c + ux * uy;
    r0.z =  uy * s - ux * uz * c + ux * uz;
    r0.w = tW[n * 3 + 0];
    r1.x =  uz * s - ux * uy * c + ux * uy;
    r1.y = (1.0f - uy * uy) * c + uy * uy;
    r1.z = -ux * s - uy * uz * c + uy * uz;
    r1.w = tW[n * 3 + 1];
    r2.x = -uy * s - ux * uz * c + ux * uz;
    r2.y =  ux * s - uy * uz * c + uy * uz;
    r2.z = (1.0f - uz * uz) * c + uz * uz;
    r2.w = tW[n * 3 + 2];
    r3 = make_float4(0.0f, 0.0f, 0.0f, 1.0f);

    // ---- stream ITER batches in bursts of GRP=8: 8 loads, 8 computes, 8 stores ----
    constexpr int STRIDE_F = N_IN * 16;        // 4096 floats per batch
    int fidx = g * (ITER * STRIDE_F) + n * 16 + (tid & 1) * 8;

#pragma unroll
    for (int jj = 0; jj < ITER / GRP; jj++) {
        V8 in[GRP];
#pragma unroll
        for (int k = 0; k < GRP; k++) in[k] = ldg256_el(I + fidx + k * STRIDE_F);

        V8 ov[GRP];
#pragma unroll
        for (int k = 0; k < GRP; k++) {
#pragma unroll
            for (int half = 0; half < 2; half++) {
                float vx = __uint_as_float(in[k].r[half * 4 + 0]);
                float vy = __uint_as_float(in[k].r[half * 4 + 1]);
                float vz = __uint_as_float(in[k].r[half * 4 + 2]);
                float vw = __uint_as_float(in[k].r[half * 4 + 3]);
                ov[k].r[half * 4 + 0] = __float_as_uint(fmaf(vx, r0.x, fmaf(vy, r1.x, fmaf(vz, r2.x, vw * r3.x))));
                ov[k].r[half * 4 + 1] = __float_as_uint(fmaf(vx, r0.y, fmaf(vy, r1.y, fmaf(vz, r2.y, vw * r3.y))));
                ov[k].r[half * 4 + 2] = __float_as_uint(fmaf(vx, r0.z, fmaf(vy, r1.z, fmaf(vz, r2.z, vw * r3.z))));
                ov[k].r[half * 4 + 3] = __float_as_uint(fmaf(vx, r0.w, fmaf(vy, r1.w, fmaf(vz, r2.w, vw * r3.w))));
            }
        }
#pragma unroll
        for (int k = 0; k < GRP; k++) stg256_ef(O + fidx + k * STRIDE_F, ov[k]);

        fidx += GRP * STRIDE_F;
    }
}

extern "C" void kernel_launch(void* const* d_in, const int* in_sizes, int n_in,
                              void* d_out, int out_size) {
    const float* I  = (const float*)d_in[0];
    const float* aW = (const float*)d_in[1];
    const float* uW = (const float*)d_in[2];
    const float* tW = (const float*)d_in[3];

    int blocks = (BATCH / ITER) * 2;   // 512
    fused_kernel<<<blocks, TPB>>>(I, aW, uW, tW, (float*)d_out);
}